// round 13
// baseline (speedup 1.0000x reference)
#include <cuda_runtime.h>
#include <cuda_fp16.h>
#include <math.h>
#include <stdint.h>

#define HH 256
#define WW 256
#define HW 65536
#define NB 16
#define CC 64
#define LL 256
#define NP 256

__device__ __half g_aH0[NB * HW * 64];
__device__ __half g_aH1[NB * HW * 64];
__device__ __half g_extra[NB * HW * 64];
__device__ __half g_wH[4 * 9 * 64 * 64];    // direct weights (layer 4 = slot 3)
__device__ __half g_wU[3 * 16 * 64 * 64];   // winograd U: [l][plane][oc][ic]
__device__ __half g_w3[128 * 32];
__device__ float g_H[NB * 21 * 256 * 2];
__device__ float g_d[NB * NP * 2];
__device__ float g_R[NB * 16 * 256 * 2];
__device__ float g_T[NB * CC * 9];
__device__ float g_Tsum[NB * CC];
__device__ float g_scale[5 * CC];
__device__ float g_bias[5 * CC];
__device__ int   g_wy[NP];
__device__ int   g_wx[NP];

#define TWO_PI 6.283185307179586f

__device__ __forceinline__ uint32_t smem_u32(const void* p) {
  uint32_t a;
  asm("{ .reg .u64 t; cvta.to.shared.u64 t, %1; cvt.u32.u64 %0, t; }" : "=r"(a) : "l"(p));
  return a;
}
#define LDM4(r, addr) \
  asm volatile("ldmatrix.sync.aligned.m8n8.x4.shared.b16 {%0,%1,%2,%3}, [%4];" \
    : "=r"((r)[0]), "=r"((r)[1]), "=r"((r)[2]), "=r"((r)[3]) : "r"(addr))
#define MMA16816(d, a, b0, b1) \
  asm volatile("mma.sync.aligned.m16n8k16.row.col.f32.f16.f16.f32 " \
    "{%0,%1,%2,%3}, {%4,%5,%6,%7}, {%8,%9}, {%0,%1,%2,%3};" \
    : "+f"((d)[0]), "+f"((d)[1]), "+f"((d)[2]), "+f"((d)[3]) \
    : "r"((a)[0]), "r"((a)[1]), "r"((a)[2]), "r"((a)[3]), "r"(b0), "r"(b1))
#define SWZ(x) ((x) ^ (((x) >> 3) & 0x70))

// direct conv_mma (layer 4) smem layout
#define SC_OFF 0
#define BI_OFF 256
#define WF_OFF 512
#define T_OFF  1280
#define TS_OFF 3584
#define ACT_H  4096
#define WGT_H  30016
#define SMEM_MMA_TOTAL 112960
#define PST 144

// winograd v2 smem layout (99328B -> 2 CTA/SM)
#define W_SC 0
#define W_BI 256
#define W_V  1024
#define W_U  66560
#define SMEM_WINO_TOTAL 99328

__global__ void prep_kernel(const float* b0, const float* g0, const float* be0,
                            const float* m0, const float* v0,
                            const float* bk, const float* gk, const float* bek,
                            const float* mk, const float* vk,
                            const float* ba, const float* ga, const float* bea,
                            const float* ma, const float* va) {
  int c = threadIdx.x;
  const float EPS = 1e-5f;
  if (c < CC) {
    float s = g0[c] * rsqrtf(v0[c] + EPS);
    g_scale[c] = s;
    g_bias[c] = be0[c] + (b0[c] - m0[c]) * s;
    for (int t = 0; t < 3; t++) {
      float st = gk[t * CC + c] * rsqrtf(vk[t * CC + c] + EPS);
      g_scale[(1 + t) * CC + c] = st;
      g_bias[(1 + t) * CC + c] = bek[t * CC + c] + (bk[t * CC + c] - mk[t * CC + c]) * st;
    }
    float sa = ga[c] * rsqrtf(va[c] + EPS);
    g_scale[4 * CC + c] = sa;
    g_bias[4 * CC + c] = bea[c] + (ba[c] - ma[c]) * sa;
  }
  if (c == 0) {
    int cnt = 0;
    for (int ch = 0; ch < CC && cnt < NP; ch++)
      for (int i = -10; i <= 10 && cnt < NP; i++)
        for (int j = -10; j <= 10; j++) {
          if (cnt >= NP) break;
          int y = 128 + i, x = 128 + j;
          if (y >= 0 && y < HH && x >= 0 && x < WW && (i * i + j * j <= 100)) {
            g_wy[cnt] = y; g_wx[cnt] = x; cnt++;
          }
        }
  }
}

__global__ void prep_w_kernel(const float* __restrict__ wk, const float* __restrict__ wa) {
  int i = blockIdx.x * 256 + threadIdx.x;
  int l = i / 36864;
  int rem = i - l * 36864;
  int t = rem / 4096;
  int r2 = rem & 4095;
  int oc = r2 >> 6, ic = r2 & 63;
  float w = (l < 3) ? wk[(((size_t)l * 64 + oc) * 64 + ic) * 9 + t]
                    : wa[((size_t)oc * 323 + 256 + ic) * 9 + t];
  g_wH[i] = __float2half(w);
}

// winograd weight transform U = G g G^T
__global__ void prep_wU_kernel(const float* __restrict__ wk) {
  int i = blockIdx.x * 256 + threadIdx.x;
  if (i >= 3 * 4096) return;
  int l = i >> 12;
  int oc = (i >> 6) & 63, ic = i & 63;
  float g[3][3];
  for (int kh = 0; kh < 3; kh++)
    for (int kw = 0; kw < 3; kw++)
      g[kh][kw] = wk[(((size_t)l * 64 + oc) * 64 + ic) * 9 + kh * 3 + kw];
  float T[4][3];
  for (int c = 0; c < 3; c++) {
    T[0][c] = g[0][c];
    T[1][c] = 0.5f * (g[0][c] + g[1][c] + g[2][c]);
    T[2][c] = 0.5f * (g[0][c] - g[1][c] + g[2][c]);
    T[3][c] = g[2][c];
  }
  for (int r = 0; r < 4; r++) {
    float U0 = T[r][0];
    float U1 = 0.5f * (T[r][0] + T[r][1] + T[r][2]);
    float U2 = 0.5f * (T[r][0] - T[r][1] + T[r][2]);
    float U3 = T[r][2];
    size_t base = (size_t)l * 65536 + (size_t)oc * 64 + ic;
    g_wU[base + (r * 4 + 0) * 4096] = __float2half(U0);
    g_wU[base + (r * 4 + 1) * 4096] = __float2half(U1);
    g_wU[base + (r * 4 + 2) * 4096] = __float2half(U2);
    g_wU[base + (r * 4 + 3) * 4096] = __float2half(U3);
  }
}

__global__ void prep_w3_kernel(const float* __restrict__ w0, const float* __restrict__ wa) {
  int i = blockIdx.x * 256 + threadIdx.x;
  if (i >= 128 * 32) return;
  int n = i >> 5, k = i & 31;
  float v = 0.f;
  if (k < 27) {
    int c = k / 9, t = k % 9, kh = t / 3, kw = t % 3;
    v = (n < 64) ? w0[((n * 3 + c) * 3 + kh) * 3 + kw]
                 : wa[(((size_t)(n - 64) * 323 + 320 + c) * 3 + kh) * 3 + kw];
  }
  g_w3[i] = __float2half(v);
}

__global__ void msgT_kernel(const float* __restrict__ message,
                            const float* __restrict__ wa) {
  int o = blockIdx.x, b = blockIdx.y;
  int c = threadIdx.x;
  __shared__ float red[8];
  float mv = message[b * LL + c];
  const float* wp = wa + ((size_t)o * 323 + c) * 9;
  float tsum = 0.f;
  for (int t = 0; t < 9; t++) {
    float v = mv * wp[t];
#pragma unroll
    for (int off = 16; off > 0; off >>= 1) v += __shfl_down_sync(0xffffffffu, v, off);
    if ((c & 31) == 0) red[c >> 5] = v;
    __syncthreads();
    if (c == 0) {
      float s = 0;
      for (int w2 = 0; w2 < 8; w2++) s += red[w2];
      g_T[(b * CC + o) * 9 + t] = s;
      tsum += s;
    }
    __syncthreads();
  }
  if (c == 0) g_Tsum[b * CC + o] = tsum;
}

// fused conv0 + layer-4 image side-field (HMMA, K=32)
#define C3_A 2160
#define C3_B 12400
#define C3_SC 22640
__launch_bounds__(256, 2)
__global__ void conv3_mma_kernel(const float* __restrict__ image) {
  __shared__ __align__(16) char s3[23152];
  float* tile = (float*)s3;
  float* sc3 = (float*)(s3 + C3_SC);
  float* bi3 = (float*)(s3 + C3_SC + 256);

  int tid = threadIdx.x, w = tid >> 5, lane = tid & 31;
  int tileX = blockIdx.x * 16, tileY = blockIdx.y * 8, b = blockIdx.z;

  for (int idx = tid; idx < 540; idx += 256) {
    int ch = idx / 180, rem = idx % 180;
    int r10 = rem / 18, c18 = rem % 18;
    int gy = tileY - 1 + r10, gx = tileX - 1 + c18;
    float v = 0.f;
    if (gy >= 0 && gy < HH && gx >= 0 && gx < WW)
      v = image[((size_t)(b * 3 + ch)) * HW + (size_t)gy * WW + gx];
    tile[idx] = v;
  }
  for (int idx = tid; idx < 2048; idx += 256) {
    int n = idx >> 4, kp = idx & 15;
    *(uint32_t*)(s3 + C3_B + n * 80 + kp * 4) = *(const uint32_t*)(g_w3 + n * 32 + kp * 2);
  }
  if (tid < 64) { sc3[tid] = g_scale[tid]; bi3[tid] = g_bias[tid]; }
  __syncthreads();

  if (tid < 128) {
    int m = tid, r = m & 7, c = m >> 3;
    __half arow[32];
#pragma unroll
    for (int ch = 0; ch < 3; ch++)
#pragma unroll
      for (int t = 0; t < 9; t++)
        arow[ch * 9 + t] = __float2half(tile[ch * 180 + (r + t / 3) * 18 + (c + t % 3)]);
#pragma unroll
    for (int k = 27; k < 32; k++) arow[k] = __float2half(0.f);
    uint4* dst = (uint4*)(s3 + C3_A + m * 80);
    dst[0] = ((uint4*)arow)[0]; dst[1] = ((uint4*)arow)[1];
    dst[2] = ((uint4*)arow)[2]; dst[3] = ((uint4*)arow)[3];
  }
  __syncthreads();

  uint32_t sb = smem_u32(s3);
  uint32_t baseA = sb + C3_A + (w * 16 + (lane & 15)) * 80 + (lane >> 4) * 16;
  uint32_t baseB = sb + C3_B + (lane & 7) * 80 + ((lane >> 3) & 1) * 16 + (lane >> 4) * 640;

  float dacc[16][4];
#pragma unroll
  for (int nb = 0; nb < 16; nb++)
#pragma unroll
    for (int q = 0; q < 4; q++) dacc[nb][q] = 0.f;

#pragma unroll
  for (int kb = 0; kb < 2; kb++) {
    uint32_t a[4];
    LDM4(a, baseA + kb * 32);
#pragma unroll
    for (int j = 0; j < 8; j++) {
      uint32_t bb[4];
      LDM4(bb, baseB + j * 1280 + kb * 32);
      MMA16816(dacc[2 * j], a, bb[0], bb[1]);
      MMA16816(dacc[2 * j + 1], a, bb[2], bb[3]);
    }
  }

  int g = lane >> 2, t4 = lane & 3;
#pragma unroll
  for (int hrow = 0; hrow < 2; hrow++) {
    int m = w * 16 + g + hrow * 8;
    int r = m & 7, c = m >> 3;
    int py = tileY + r, px = tileX + c;
    size_t pix = (size_t)b * HW + (size_t)py * WW + px;
#pragma unroll
    for (int nb = 0; nb < 8; nb++) {
      int ch = nb * 8 + t4 * 2;
      float v0 = dacc[nb][hrow * 2] * sc3[ch] + bi3[ch];
      float v1 = dacc[nb][hrow * 2 + 1] * sc3[ch + 1] + bi3[ch + 1];
      v0 = v0 > 0.f ? v0 : 0.f;
      v1 = v1 > 0.f ? v1 : 0.f;
      *(__half2*)(g_aH0 + pix * 64 + ch) = __halves2half2(__float2half(v0), __float2half(v1));
    }
#pragma unroll
    for (int nb = 8; nb < 16; nb++) {
      int oce = (nb - 8) * 8 + t4 * 2;
      *(__half2*)(g_extra + pix * 64 + oce) =
          __halves2half2(__float2half(dacc[nb][hrow * 2]), __float2half(dacc[nb][hrow * 2 + 1]));
    }
  }
}

// ------------- Winograd v2: V from gmem, U streamed, 2 CTA/SM --------------
__launch_bounds__(256, 2)
__global__ void conv_wino_kernel(int srcSel, int wslot, int layer) {
  extern __shared__ __align__(16) char smem[];
  float* sc_s = (float*)(smem + W_SC);
  float* bi_s = (float*)(smem + W_BI);

  int tid = threadIdx.x, w = tid >> 5, lane = tid & 31;
  int mg = w >> 2, nq = w & 3;
  int tileX = blockIdx.x * 16, b = blockIdx.z;

  const __half* inH = srcSel ? g_aH1 : g_aH0;
  __half* outH = srcSel ? g_aH0 : g_aH1;
  const __half* Usrc = g_wU + (size_t)wslot * 65536;

  if (tid < 64) { sc_s[tid] = g_scale[layer * CC + tid]; bi_s[tid] = g_bias[layer * CC + tid]; }

  // initial: stage U group 0 (planes 0,1) into buf0
#pragma unroll
  for (int j = 0; j < 4; j++) {
    int idx = tid + 256 * j;
    int pig = idx >> 9;
    int i = idx & 511;
    uint4 v = *(const uint4*)(Usrc + (size_t)pig * 4096 + (i >> 3) * 64 + (i & 7) * 8);
    *(uint4*)(smem + W_U + pig * 8192 + SWZ((i >> 3) * 128 + (i & 7) * 16)) = v;
  }

  uint32_t sb = smem_u32(smem);
  int rowA = mg * 16 + (lane & 15);
  int koffA = (lane >> 4) * 16;
  int rowB = nq * 16 + (lane & 7) + ((lane >> 4) << 3);
  int koffB = ((lane >> 3) & 1) * 16;
  static const int A0c[4] = {1, 1, 1, 0};
  static const int A1c[4] = {0, 1, -1, -1};
  int gl = lane >> 2, t4 = lane & 3;

  for (int yt = 0; yt < 4; yt++) {
    int tileY = (blockIdx.y * 4 + yt) * 8;

    // build V for all 16 planes directly from gmem
#pragma unroll
    for (int k = 0; k < 4; k++) {
      int id = tid + 256 * k;
      int tile = id >> 5, icp = id & 31;
      int tr = tile >> 3, tc = tile & 7;
      int gy0 = tileY - 1 + 2 * tr, gx0 = tileX - 1 + 2 * tc;
      __half2 d[4][4];
#pragma unroll
      for (int i2 = 0; i2 < 4; i2++) {
        int gy = gy0 + i2;
        bool vy = (gy >= 0) && (gy < HH);
#pragma unroll
        for (int j2 = 0; j2 < 4; j2++) {
          int gx = gx0 + j2;
          __half2 v = __halves2half2(__float2half(0.f), __float2half(0.f));
          if (vy && gx >= 0 && gx < WW)
            v = *(const __half2*)(inH + (((size_t)b * HW + (size_t)gy * WW + gx) * 64 + icp * 2));
          d[i2][j2] = v;
        }
      }
      __half2 e[4][4];
#pragma unroll
      for (int j2 = 0; j2 < 4; j2++) {
        e[0][j2] = __hsub2(d[0][j2], d[2][j2]);
        e[1][j2] = __hadd2(d[1][j2], d[2][j2]);
        e[2][j2] = __hsub2(d[2][j2], d[1][j2]);
        e[3][j2] = __hsub2(d[1][j2], d[3][j2]);
      }
      uint32_t voff = SWZ((uint32_t)(tile * 128 + icp * 4));
#pragma unroll
      for (int i2 = 0; i2 < 4; i2++) {
        *(__half2*)(smem + W_V + (i2 * 4 + 0) * 4096 + voff) = __hsub2(e[i2][0], e[i2][2]);
        *(__half2*)(smem + W_V + (i2 * 4 + 1) * 4096 + voff) = __hadd2(e[i2][1], e[i2][2]);
        *(__half2*)(smem + W_V + (i2 * 4 + 2) * 4096 + voff) = __hsub2(e[i2][2], e[i2][1]);
        *(__half2*)(smem + W_V + (i2 * 4 + 3) * 4096 + voff) = __hsub2(e[i2][1], e[i2][3]);
      }
    }
    __syncthreads();

    float o[2][2][8];
#pragma unroll
    for (int p = 0; p < 2; p++)
#pragma unroll
      for (int q = 0; q < 2; q++)
#pragma unroll
        for (int k = 0; k < 8; k++) o[p][q][k] = 0.f;

#pragma unroll
    for (int g = 0; g < 8; g++) {
      // prefetch next U group
      uint4 pre[4];
      int gn = (g + 1) & 7;
#pragma unroll
      for (int j = 0; j < 4; j++) {
        int idx = tid + 256 * j;
        int pig = idx >> 9;
        int i = idx & 511;
        pre[j] = *(const uint4*)(Usrc + (size_t)(2 * gn + pig) * 4096 + (i >> 3) * 64 + (i & 7) * 8);
      }

#pragma unroll
      for (int pig = 0; pig < 2; pig++) {
        int xi = 2 * g + pig;
        float macc[8];
#pragma unroll
        for (int k = 0; k < 8; k++) macc[k] = 0.f;
        uint32_t Vp = sb + W_V + xi * 4096;
        uint32_t Up = sb + W_U + (g & 1) * 16384 + pig * 8192;
#pragma unroll
        for (int kb = 0; kb < 4; kb++) {
          uint32_t a[4], bb[4];
          LDM4(a, Vp + SWZ((uint32_t)(rowA * 128 + koffA + kb * 32)));
          LDM4(bb, Up + SWZ((uint32_t)(rowB * 128 + koffB + kb * 32)));
          MMA16816(macc, a, bb[0], bb[1]);
          MMA16816(macc + 4, a, bb[2], bb[3]);
        }
        int ii = xi >> 2, jj = xi & 3;
#pragma unroll
        for (int p = 0; p < 2; p++) {
          int ci = p ? A1c[ii] : A0c[ii];
          if (ci == 0) continue;
#pragma unroll
          for (int q = 0; q < 2; q++) {
            int cj = q ? A1c[jj] : A0c[jj];
            int c = ci * cj;
            if (c == 1) {
#pragma unroll
              for (int k = 0; k < 8; k++) o[p][q][k] += macc[k];
            } else if (c == -1) {
#pragma unroll
              for (int k = 0; k < 8; k++) o[p][q][k] -= macc[k];
            }
          }
        }
      }
      __syncthreads();
#pragma unroll
      for (int j = 0; j < 4; j++) {
        int idx = tid + 256 * j;
        int pig = idx >> 9;
        int i = idx & 511;
        *(uint4*)(smem + W_U + ((g + 1) & 1) * 16384 + pig * 8192 + SWZ((i >> 3) * 128 + (i & 7) * 16)) = pre[j];
      }
      __syncthreads();
    }

    // epilogue: BN + ReLU + fp16 store
#pragma unroll
    for (int hrow = 0; hrow < 2; hrow++) {
      int m = mg * 16 + gl + 8 * hrow;
      int tr = m >> 3, tc = m & 7;
#pragma unroll
      for (int p = 0; p < 2; p++) {
        int py = tileY + 2 * tr + p;
#pragma unroll
        for (int q = 0; q < 2; q++) {
          int px = tileX + 2 * tc + q;
          size_t pix = (size_t)b * HW + (size_t)py * WW + px;
#pragma unroll
          for (int nb = 0; nb < 2; nb++) {
            int ch = nq * 16 + nb * 8 + t4 * 2;
            float v0 = o[p][q][nb * 4 + hrow * 2] * sc_s[ch] + bi_s[ch];
            float v1 = o[p][q][nb * 4 + hrow * 2 + 1] * sc_s[ch + 1] + bi_s[ch + 1];
            v0 = v0 > 0.f ? v0 : 0.f;
            v1 = v1 > 0.f ? v1 : 0.f;
            *(__half2*)(outH + pix * 64 + ch) = __halves2half2(__float2half(v0), __float2half(v1));
          }
        }
      }
    }
  }
}

// direct HMMA conv (layer 4: extra + msg taps + proj)
__launch_bounds__(256, 2)
__global__ void conv_mma_kernel(int srcSel, int wslot, int layer,
                                int use_extra, int do_proj,
                                const float* __restrict__ wf,
                                const float* __restrict__ bf,
                                float* __restrict__ out) {
  extern __shared__ __align__(16) char smem[];
  float* sc_s = (float*)(smem + SC_OFF);
  float* bi_s = (float*)(smem + BI_OFF);
  float* wf_s = (float*)(smem + WF_OFF);
  float* T_s = (float*)(smem + T_OFF);
  float* Ts_s = (float*)(smem + TS_OFF);

  int tid = threadIdx.x, w = tid >> 5, lane = tid & 31;
  int tileX = blockIdx.x * 16, b = blockIdx.z;

  const __half* inH = srcSel ? g_aH1 : g_aH0;
  __half* outH = srcSel ? g_aH0 : g_aH1;
  const __half* wHs = g_wH + wslot * 36864;

  for (int i = tid; i < 4608; i += 256) {
    int t = i >> 9;
    int oc = (i >> 3) & 63;
    int ich = i & 7;
    uint4 v = *(const uint4*)(wHs + ((size_t)(t * 64 + oc) * 64 + ich * 8));
    *(uint4*)(smem + WGT_H + t * 9216 + oc * PST + ich * 16) = v;
  }
  if (tid < 64) { sc_s[tid] = g_scale[layer * CC + tid]; bi_s[tid] = g_bias[layer * CC + tid]; }
  if (do_proj && tid >= 64 && tid < 256) wf_s[tid - 64] = wf[tid - 64];
  if (use_extra) {
    for (int i = tid; i < 576; i += 256) T_s[i] = g_T[b * 576 + i];
    if (tid < 64) Ts_s[tid] = g_Tsum[b * CC + tid];
  }

  uint32_t sb = smem_u32(smem);
  int mL = lane & 15;
  int rL = mL & 7, cL = w * 2 + (mL >> 3);
  uint32_t baseA = (uint32_t)((rL * 18 + cL) * PST + (lane >> 4) * 16);
  uint32_t baseB = (uint32_t)((lane & 7) * PST + ((lane >> 3) & 1) * 16 + (lane >> 4) * (8 * PST));
  int g = lane >> 2, t4 = lane & 3;

  {
    int tileY0 = (blockIdx.y * 4) * 8;
    for (int i = tid; i < 1440; i += 256) {
      int r10 = i / 144;
      int rem = i - r10 * 144;
      int c18 = rem >> 3, och = rem & 7;
      int gy = tileY0 - 1 + r10, gx = tileX - 1 + c18;
      uint4 v = make_uint4(0, 0, 0, 0);
      if (gy >= 0 && gy < HH && gx >= 0 && gx < WW)
        v = *(const uint4*)(inH + (((size_t)b * HW + (size_t)gy * WW + gx) * 64 + och * 8));
      *(uint4*)(smem + ACT_H + (r10 * 18 + c18) * PST + och * 16) = v;
    }
  }
  __syncthreads();

  for (int yt = 0; yt < 4; yt++) {
    int tileY = (blockIdx.y * 4 + yt) * 8;

    uint4 pre[6];
    if (yt < 3) {
      int tileYn = tileY + 8;
#pragma unroll
      for (int i2 = 0; i2 < 6; i2++) {
        int idx = tid + 256 * i2;
        uint4 v = make_uint4(0, 0, 0, 0);
        if (idx < 1440) {
          int r10 = idx / 144;
          int rem = idx - r10 * 144;
          int c18 = rem >> 3, och = rem & 7;
          int gy = tileYn - 1 + r10, gx = tileX - 1 + c18;
          if (gy >= 0 && gy < HH && gx >= 0 && gx < WW)
            v = *(const uint4*)(inH + (((size_t)b * HW + (size_t)gy * WW + gx) * 64 + och * 8));
        }
        pre[i2] = v;
      }
    }

    float dacc[8][4];
#pragma unroll
    for (int nb = 0; nb < 8; nb++)
#pragma unroll
      for (int q = 0; q < 4; q++) dacc[nb][q] = 0.f;

    for (int t = 0; t < 9; t++) {
      int toff = ((t / 3) * 18 + (t % 3)) * PST;
      uint32_t aH_t = sb + ACT_H + baseA + toff;
      uint32_t wH_t = sb + WGT_H + t * 9216 + baseB;
#pragma unroll
      for (int kb = 0; kb < 4; kb++) {
        uint32_t ah[4], bh[4][4];
        LDM4(ah, aH_t + kb * 32);
#pragma unroll
        for (int j = 0; j < 4; j++) LDM4(bh[j], wH_t + j * 2304 + kb * 32);
#pragma unroll
        for (int j = 0; j < 4; j++) {
          MMA16816(dacc[2 * j], ah, bh[j][0], bh[j][1]);
          MMA16816(dacc[2 * j + 1], ah, bh[j][2], bh[j][3]);
        }
      }
    }

    __syncthreads();
    if (yt < 3) {
#pragma unroll
      for (int i2 = 0; i2 < 6; i2++) {
        int idx = tid + 256 * i2;
        if (idx < 1440) {
          int r10 = idx / 144;
          int rem = idx - r10 * 144;
          int c18 = rem >> 3, och = rem & 7;
          *(uint4*)(smem + ACT_H + (r10 * 18 + c18) * PST + och * 16) = pre[i2];
        }
      }
      __syncthreads();
    }

#pragma unroll
    for (int hrow = 0; hrow < 2; hrow++) {
      int mloc = w * 16 + g + hrow * 8;
      int r = mloc & 7, c = mloc >> 3;
      int py = tileY + r, px = tileX + c;
      size_t pix = (size_t)b * HW + (size_t)py * WW + px;
      float v[16];
#pragma unroll
      for (int nb = 0; nb < 8; nb++) {
        v[2 * nb] = dacc[nb][hrow * 2];
        v[2 * nb + 1] = dacc[nb][hrow * 2 + 1];
      }
      if (use_extra) {
#pragma unroll
        for (int nb = 0; nb < 8; nb++) {
          __half2 e = *(const __half2*)(g_extra + pix * 64 + nb * 8 + t4 * 2);
          v[2 * nb] += __half2float(__low2half(e));
          v[2 * nb + 1] += __half2float(__high2half(e));
        }
        bool interior = (py >= 1 && py <= 254 && px >= 1 && px <= 254);
        if (interior) {
#pragma unroll
          for (int i = 0; i < 16; i++) {
            int ch = (i >> 1) * 8 + t4 * 2 + (i & 1);
            v[i] += Ts_s[ch];
          }
        } else {
          bool vy[3] = {py >= 1, true, py <= 254};
          bool vx[3] = {px >= 1, true, px <= 254};
#pragma unroll
          for (int i = 0; i < 16; i++) {
            int ch = (i >> 1) * 8 + t4 * 2 + (i & 1);
            float s = 0.f;
#pragma unroll
            for (int t = 0; t < 9; t++)
              if (vy[t / 3] && vx[t % 3]) s += T_s[ch * 9 + t];
            v[i] += s;
          }
        }
      }
#pragma unroll
      for (int i = 0; i < 16; i++) {
        int ch = (i >> 1) * 8 + t4 * 2 + (i & 1);
        float val = v[i] * sc_s[ch] + bi_s[ch];
        v[i] = val > 0.f ? val : 0.f;
      }
      if (do_proj) {
        float p0 = 0.f, p1 = 0.f, p2 = 0.f;
#pragma unroll
        for (int i = 0; i < 16; i++) {
          int ch = (i >> 1) * 8 + t4 * 2 + (i & 1);
          p0 += v[i] * wf_s[ch];
          p1 += v[i] * wf_s[64 + ch];
          p2 += v[i] * wf_s[128 + ch];
        }
#pragma unroll
        for (int m2 = 1; m2 <= 2; m2 <<= 1) {
          p0 += __shfl_xor_sync(0xffffffffu, p0, m2);
          p1 += __shfl_xor_sync(0xffffffffu, p1, m2);
          p2 += __shfl_xor_sync(0xffffffffu, p2, m2);
        }
        if (t4 == 0) {
          size_t ob = ((size_t)b * 3) * HW + (size_t)py * WW + px;
          out[ob] = p0 + bf[0];
          out[ob + HW] = p1 + bf[1];
          out[ob + 2 * HW] = p2 + bf[2];
        }
      } else {
#pragma unroll
        for (int nb = 0; nb < 8; nb++) {
          int ch = nb * 8 + t4 * 2;
          *(__half2*)(outH + pix * 64 + ch) =
              __halves2half2(__float2half(v[2 * nb]), __float2half(v[2 * nb + 1]));
        }
      }
    }
  }
}

__global__ void dft_rows_kernel() {
  int n = blockIdx.x, b = blockIdx.y;
  int m = threadIdx.x;
  __shared__ float row[256], twc[256], tws[256], red[16];
  float s, c;
  sincosf((float)m * (TWO_PI / 256.f), &s, &c);
  twc[m] = c; tws[m] = s;
  size_t off = ((size_t)b * HW + (size_t)n * WW + m) * 64;
  row[m] = __half2float(g_aH1[off]);
  __syncthreads();
  float x = row[m];
  int lane = m & 31, wid = m >> 5;
  for (int f = 0; f < 21; f++) {
    int idx = ((118 + f) * m) & 255;
    float pr = x * twc[idx];
    float pi = -x * tws[idx];
#pragma unroll
    for (int o2 = 16; o2 > 0; o2 >>= 1) {
      pr += __shfl_down_sync(0xffffffffu, pr, o2);
      pi += __shfl_down_sync(0xffffffffu, pi, o2);
    }
    if (lane == 0) { red[wid] = pr; red[8 + wid] = pi; }
    __syncthreads();
    if (m == 0) {
      float sr = 0, si = 0;
      for (int w = 0; w < 8; w++) { sr += red[w]; si += red[8 + w]; }
      g_H[((size_t)(b * 21 + f) * 256 + n) * 2] = sr;
      g_H[((size_t)(b * 21 + f) * 256 + n) * 2 + 1] = si;
    }
    __syncthreads();
  }
}

__global__ void dft_points_kernel(const float* __restrict__ message) {
  int b = blockIdx.x;
  int p = threadIdx.x;
  __shared__ float twc[256], tws[256];
  float s, c;
  sincosf((float)p * (TWO_PI / 256.f), &s, &c);
  twc[p] = c; tws[p] = s;
  __syncthreads();
  int yp = g_wy[p], xp = g_wx[p];
  int f = xp - 118;
  const float* Hp = g_H + (size_t)(b * 21 + f) * 512;
  float Fr = 0, Fi = 0;
  for (int n = 0; n < 256; n++) {
    int idx = (yp * n) & 255;
    float cc = twc[idx], ss = tws[idx];
    float hr = Hp[n * 2], hi = Hp[n * 2 + 1];
    Fr += hr * cc + hi * ss;
    Fi += hi * cc - hr * ss;
  }
  float mv = message[b * LL + p];
  g_d[(b * NP + p) * 2] = mv - Fr;
  g_d[(b * NP + p) * 2 + 1] = mv - Fi;
}

__global__ void dft_R_kernel() {
  int yf = blockIdx.x, b = blockIdx.y;
  int m = threadIdx.x;
  __shared__ float twc[256], tws[256], dsr[256], dsi[256];
  float s, c;
  sincosf((float)m * (TWO_PI / 256.f), &s, &c);
  twc[m] = c; tws[m] = s;
  dsr[m] = g_d[(b * NP + m) * 2];
  dsi[m] = g_d[(b * NP + m) * 2 + 1];
  __syncthreads();
  int yv = 118 + yf;
  float ar = 0, ai = 0;
  for (int p = 0; p < NP; p++) {
    if (g_wy[p] == yv) {
      int idx = (g_wx[p] * m) & 255;
      float cc = twc[idx], ss = tws[idx];
      float dr = dsr[p], di = dsi[p];
      ar += dr * cc - di * ss;
      ai += dr * ss + di * cc;
    }
  }
  g_R[((size_t)(b * 16 + yf) * 256 + m) * 2] = ar;
  g_R[((size_t)(b * 16 + yf) * 256 + m) * 2 + 1] = ai;
}

__global__ void dft_corr_kernel() {
  int n = blockIdx.x, b = blockIdx.y;
  int m = threadIdx.x;
  __shared__ float twc[256], tws[256];
  float s, c;
  sincosf((float)m * (TWO_PI / 256.f), &s, &c);
  twc[m] = c; tws[m] = s;
  __syncthreads();
  float acc = 0.f;
#pragma unroll
  for (int yf = 0; yf < 16; yf++) {
    int idx = ((118 + yf) * n) & 255;
    float cc = twc[idx], ss = tws[idx];
    float Rr = g_R[((size_t)(b * 16 + yf) * 256 + m) * 2];
    float Ri = g_R[((size_t)(b * 16 + yf) * 256 + m) * 2 + 1];
    acc += cc * Rr - ss * Ri;
  }
  size_t off = ((size_t)b * HW + (size_t)n * WW + m) * 64;
  float v = __half2float(g_aH1[off]) + acc * (1.0f / 65536.0f);
  g_aH1[off] = __float2half(v);
}

extern "C" void kernel_launch(void* const* d_in, const int* in_sizes, int n_in,
                              void* d_out, int out_size) {
  const float* image   = (const float*)d_in[0];
  const float* message = (const float*)d_in[1];
  const float* w0  = (const float*)d_in[2];
  const float* b0  = (const float*)d_in[3];
  const float* g0  = (const float*)d_in[4];
  const float* be0 = (const float*)d_in[5];
  const float* m0  = (const float*)d_in[6];
  const float* v0  = (const float*)d_in[7];
  const float* wk  = (const float*)d_in[8];
  const float* bk  = (const float*)d_in[9];
  const float* gk  = (const float*)d_in[10];
  const float* bek = (const float*)d_in[11];
  const float* mk  = (const float*)d_in[12];
  const float* vk  = (const float*)d_in[13];
  const float* wa  = (const float*)d_in[14];
  const float* ba  = (const float*)d_in[15];
  const float* ga  = (const float*)d_in[16];
  const float* bea = (const float*)d_in[17];
  const float* ma  = (const float*)d_in[18];
  const float* va  = (const float*)d_in[19];
  const float* wf  = (const float*)d_in[20];
  const float* bf  = (const float*)d_in[21];
  float* out = (float*)d_out;

  cudaFuncSetAttribute(conv_mma_kernel, cudaFuncAttributeMaxDynamicSharedMemorySize, SMEM_MMA_TOTAL);
  cudaFuncSetAttribute(conv_wino_kernel, cudaFuncAttributeMaxDynamicSharedMemorySize, SMEM_WINO_TOTAL);

  prep_kernel<<<1, 256>>>(b0, g0, be0, m0, v0, bk, gk, bek, mk, vk, ba, ga, bea, ma, va);
  prep_w_kernel<<<576, 256>>>(wk, wa);
  prep_wU_kernel<<<48, 256>>>(wk);
  prep_w3_kernel<<<16, 256>>>(w0, wa);
  msgT_kernel<<<dim3(64, NB), 256>>>(message, wa);

  conv3_mma_kernel<<<dim3(16, 32, NB), 256>>>(image);

  dim3 wg(16, 8, NB);
  conv_wino_kernel<<<wg, 256, SMEM_WINO_TOTAL>>>(0, 0, 1);
  conv_wino_kernel<<<wg, 256, SMEM_WINO_TOTAL>>>(1, 1, 2);
  conv_wino_kernel<<<wg, 256, SMEM_WINO_TOTAL>>>(0, 2, 3);

  dft_rows_kernel<<<dim3(256, NB), 256>>>();
  dft_points_kernel<<<NB, 256>>>(message);
  dft_R_kernel<<<dim3(16, NB), 256>>>();
  dft_corr_kernel<<<dim3(256, NB), 256>>>();

  conv_mma_kernel<<<dim3(16, 8, NB), 256, SMEM_MMA_TOTAL>>>(1, 3, 4, 1, 1, wf, bf, out);
}

// round 14
// speedup vs baseline: 1.0236x; 1.0236x over previous
#include <cuda_runtime.h>
#include <cuda_fp16.h>
#include <math.h>
#include <stdint.h>

#define HH 256
#define WW 256
#define HW 65536
#define NB 16
#define CC 64
#define LL 256
#define NP 256

__device__ __half g_aH0[NB * HW * 64];
__device__ __half g_aH1[NB * HW * 64];
__device__ __half g_extra[NB * HW * 64];    // layer-4 image side field (fp16)
__device__ __half g_wH[4 * 9 * 64 * 64];    // [slot][tap][oc][ic] fp16
__device__ __half g_w3[128 * 32];           // conv0+side fused B
__device__ float g_H[NB * 21 * 256 * 2];
__device__ float g_d[NB * NP * 2];
__device__ float g_R[NB * 16 * 256 * 2];
__device__ float g_T[NB * CC * 9];
__device__ float g_Tsum[NB * CC];
__device__ float g_scale[5 * CC];
__device__ float g_bias[5 * CC];
__device__ int   g_wy[NP];
__device__ int   g_wx[NP];

#define TWO_PI 6.283185307179586f

__device__ __forceinline__ uint32_t smem_u32(const void* p) {
  uint32_t a;
  asm("{ .reg .u64 t; cvta.to.shared.u64 t, %1; cvt.u32.u64 %0, t; }" : "=r"(a) : "l"(p));
  return a;
}
#define LDM4(r, addr) \
  asm volatile("ldmatrix.sync.aligned.m8n8.x4.shared.b16 {%0,%1,%2,%3}, [%4];" \
    : "=r"((r)[0]), "=r"((r)[1]), "=r"((r)[2]), "=r"((r)[3]) : "r"(addr))
#define MMA16816(d, a, b0, b1) \
  asm volatile("mma.sync.aligned.m16n8k16.row.col.f32.f16.f16.f32 " \
    "{%0,%1,%2,%3}, {%4,%5,%6,%7}, {%8,%9}, {%0,%1,%2,%3};" \
    : "+f"((d)[0]), "+f"((d)[1]), "+f"((d)[2]), "+f"((d)[3]) \
    : "r"((a)[0]), "r"((a)[1]), "r"((a)[2]), "r"((a)[3]), "r"(b0), "r"(b1))

// conv_mma smem layout
#define SC_OFF 0
#define BI_OFF 256
#define WF_OFF 512
#define T_OFF  1280
#define TS_OFF 3584
#define ACT_H  4096
#define WGT_H  30016
#define SMEM_MMA_TOTAL 112960
#define PST 144

__global__ void prep_kernel(const float* b0, const float* g0, const float* be0,
                            const float* m0, const float* v0,
                            const float* bk, const float* gk, const float* bek,
                            const float* mk, const float* vk,
                            const float* ba, const float* ga, const float* bea,
                            const float* ma, const float* va) {
  int c = threadIdx.x;
  const float EPS = 1e-5f;
  if (c < CC) {
    float s = g0[c] * rsqrtf(v0[c] + EPS);
    g_scale[c] = s;
    g_bias[c] = be0[c] + (b0[c] - m0[c]) * s;
    for (int t = 0; t < 3; t++) {
      float st = gk[t * CC + c] * rsqrtf(vk[t * CC + c] + EPS);
      g_scale[(1 + t) * CC + c] = st;
      g_bias[(1 + t) * CC + c] = bek[t * CC + c] + (bk[t * CC + c] - mk[t * CC + c]) * st;
    }
    float sa = ga[c] * rsqrtf(va[c] + EPS);
    g_scale[4 * CC + c] = sa;
    g_bias[4 * CC + c] = bea[c] + (ba[c] - ma[c]) * sa;
  }
  if (c == 0) {
    int cnt = 0;
    for (int ch = 0; ch < CC && cnt < NP; ch++)
      for (int i = -10; i <= 10 && cnt < NP; i++)
        for (int j = -10; j <= 10; j++) {
          if (cnt >= NP) break;
          int y = 128 + i, x = 128 + j;
          if (y >= 0 && y < HH && x >= 0 && x < WW && (i * i + j * j <= 100)) {
            g_wy[cnt] = y; g_wx[cnt] = x; cnt++;
          }
        }
  }
}

__global__ void prep_w_kernel(const float* __restrict__ wk, const float* __restrict__ wa) {
  int i = blockIdx.x * 256 + threadIdx.x;
  int l = i / 36864;
  int rem = i - l * 36864;
  int t = rem / 4096;
  int r2 = rem & 4095;
  int oc = r2 >> 6, ic = r2 & 63;
  float w = (l < 3) ? wk[(((size_t)l * 64 + oc) * 64 + ic) * 9 + t]
                    : wa[((size_t)oc * 323 + 256 + ic) * 9 + t];
  g_wH[i] = __float2half(w);
}

__global__ void prep_w3_kernel(const float* __restrict__ w0, const float* __restrict__ wa) {
  int i = blockIdx.x * 256 + threadIdx.x;
  if (i >= 128 * 32) return;
  int n = i >> 5, k = i & 31;
  float v = 0.f;
  if (k < 27) {
    int c = k / 9, t = k % 9, kh = t / 3, kw = t % 3;
    v = (n < 64) ? w0[((n * 3 + c) * 3 + kh) * 3 + kw]
                 : wa[(((size_t)(n - 64) * 323 + 320 + c) * 3 + kh) * 3 + kw];
  }
  g_w3[i] = __float2half(v);
}

// warp-per-oc, shfl-only reduction (no block barriers)
__global__ void msgT_kernel(const float* __restrict__ message,
                            const float* __restrict__ wa) {
  int w = threadIdx.x >> 5, lane = threadIdx.x & 31;
  int o = blockIdx.x * 8 + w, b = blockIdx.y;
  float mv[8];
#pragma unroll
  for (int i = 0; i < 8; i++) mv[i] = message[b * LL + lane * 8 + i];
  const float* wp = wa + (size_t)o * 323 * 9;
  float tsum = 0.f;
  for (int t = 0; t < 9; t++) {
    float v = 0.f;
#pragma unroll
    for (int i = 0; i < 8; i++) v += mv[i] * wp[(lane * 8 + i) * 9 + t];
#pragma unroll
    for (int off = 16; off > 0; off >>= 1) v += __shfl_down_sync(0xffffffffu, v, off);
    if (lane == 0) {
      g_T[(b * CC + o) * 9 + t] = v;
      tsum += v;
    }
  }
  if (lane == 0) g_Tsum[b * CC + o] = tsum;
}

// fused conv0 + layer-4 image side-field via HMMA implicit GEMM (K=32).
#define C3_A 2160
#define C3_B 12400
#define C3_SC 22640
__launch_bounds__(256, 2)
__global__ void conv3_mma_kernel(const float* __restrict__ image) {
  __shared__ __align__(16) char s3[23152];
  float* tile = (float*)s3;
  float* sc3 = (float*)(s3 + C3_SC);
  float* bi3 = (float*)(s3 + C3_SC + 256);

  int tid = threadIdx.x, w = tid >> 5, lane = tid & 31;
  int tileX = blockIdx.x * 16, tileY = blockIdx.y * 8, b = blockIdx.z;

  for (int idx = tid; idx < 540; idx += 256) {
    int ch = idx / 180, rem = idx % 180;
    int r10 = rem / 18, c18 = rem % 18;
    int gy = tileY - 1 + r10, gx = tileX - 1 + c18;
    float v = 0.f;
    if (gy >= 0 && gy < HH && gx >= 0 && gx < WW)
      v = image[((size_t)(b * 3 + ch)) * HW + (size_t)gy * WW + gx];
    tile[idx] = v;
  }
  for (int idx = tid; idx < 2048; idx += 256) {
    int n = idx >> 4, kp = idx & 15;
    *(uint32_t*)(s3 + C3_B + n * 80 + kp * 4) = *(const uint32_t*)(g_w3 + n * 32 + kp * 2);
  }
  if (tid < 64) { sc3[tid] = g_scale[tid]; bi3[tid] = g_bias[tid]; }
  __syncthreads();

  if (tid < 128) {
    int m = tid, r = m & 7, c = m >> 3;
    __half arow[32];
#pragma unroll
    for (int ch = 0; ch < 3; ch++)
#pragma unroll
      for (int t = 0; t < 9; t++)
        arow[ch * 9 + t] = __float2half(tile[ch * 180 + (r + t / 3) * 18 + (c + t % 3)]);
#pragma unroll
    for (int k = 27; k < 32; k++) arow[k] = __float2half(0.f);
    uint4* dst = (uint4*)(s3 + C3_A + m * 80);
    dst[0] = ((uint4*)arow)[0]; dst[1] = ((uint4*)arow)[1];
    dst[2] = ((uint4*)arow)[2]; dst[3] = ((uint4*)arow)[3];
  }
  __syncthreads();

  uint32_t sb = smem_u32(s3);
  uint32_t baseA = sb + C3_A + (w * 16 + (lane & 15)) * 80 + (lane >> 4) * 16;
  uint32_t baseB = sb + C3_B + (lane & 7) * 80 + ((lane >> 3) & 1) * 16 + (lane >> 4) * 640;

  float dacc[16][4];
#pragma unroll
  for (int nb = 0; nb < 16; nb++)
#pragma unroll
    for (int q = 0; q < 4; q++) dacc[nb][q] = 0.f;

#pragma unroll
  for (int kb = 0; kb < 2; kb++) {
    uint32_t a[4];
    LDM4(a, baseA + kb * 32);
#pragma unroll
    for (int j = 0; j < 8; j++) {
      uint32_t bb[4];
      LDM4(bb, baseB + j * 1280 + kb * 32);
      MMA16816(dacc[2 * j], a, bb[0], bb[1]);
      MMA16816(dacc[2 * j + 1], a, bb[2], bb[3]);
    }
  }

  int g = lane >> 2, t4 = lane & 3;
#pragma unroll
  for (int hrow = 0; hrow < 2; hrow++) {
    int m = w * 16 + g + hrow * 8;
    int r = m & 7, c = m >> 3;
    int py = tileY + r, px = tileX + c;
    size_t pix = (size_t)b * HW + (size_t)py * WW + px;
#pragma unroll
    for (int nb = 0; nb < 8; nb++) {
      int ch = nb * 8 + t4 * 2;
      float v0 = dacc[nb][hrow * 2] * sc3[ch] + bi3[ch];
      float v1 = dacc[nb][hrow * 2 + 1] * sc3[ch + 1] + bi3[ch + 1];
      v0 = v0 > 0.f ? v0 : 0.f;
      v1 = v1 > 0.f ? v1 : 0.f;
      *(__half2*)(g_aH0 + pix * 64 + ch) = __halves2half2(__float2half(v0), __float2half(v1));
    }
#pragma unroll
    for (int nb = 8; nb < 16; nb++) {
      int oce = (nb - 8) * 8 + t4 * 2;
      *(__half2*)(g_extra + pix * 64 + oce) =
          __halves2half2(__float2half(dacc[nb][hrow * 2]), __float2half(dacc[nb][hrow * 2 + 1]));
    }
  }
}

// HMMA fp16 1-pass implicit-GEMM 3x3 conv, 64ic->64oc. 2 CTAs/SM, double-buffered staging.
__launch_bounds__(256, 2)
__global__ void conv_mma_kernel(int srcSel, int wslot, int layer,
                                int use_extra, int do_proj,
                                const float* __restrict__ wf,
                                const float* __restrict__ bf,
                                float* __restrict__ out) {
  extern __shared__ __align__(16) char smem[];
  float* sc_s = (float*)(smem + SC_OFF);
  float* bi_s = (float*)(smem + BI_OFF);
  float* wf_s = (float*)(smem + WF_OFF);
  float* T_s = (float*)(smem + T_OFF);
  float* Ts_s = (float*)(smem + TS_OFF);

  int tid = threadIdx.x, w = tid >> 5, lane = tid & 31;
  int tileX = blockIdx.x * 16, b = blockIdx.z;

  const __half* inH = srcSel ? g_aH1 : g_aH0;
  __half* outH = srcSel ? g_aH0 : g_aH1;
  const __half* wHs = g_wH + wslot * 36864;

  for (int i = tid; i < 4608; i += 256) {
    int t = i >> 9;
    int oc = (i >> 3) & 63;
    int ich = i & 7;
    uint4 v = *(const uint4*)(wHs + ((size_t)(t * 64 + oc) * 64 + ich * 8));
    *(uint4*)(smem + WGT_H + t * 9216 + oc * PST + ich * 16) = v;
  }
  if (tid < 64) { sc_s[tid] = g_scale[layer * CC + tid]; bi_s[tid] = g_bias[layer * CC + tid]; }
  if (do_proj && tid >= 64 && tid < 256) wf_s[tid - 64] = wf[tid - 64];
  if (use_extra) {
    for (int i = tid; i < 576; i += 256) T_s[i] = g_T[b * 576 + i];
    if (tid < 64) Ts_s[tid] = g_Tsum[b * CC + tid];
  }

  uint32_t sb = smem_u32(smem);
  int mL = lane & 15;
  int rL = mL & 7, cL = w * 2 + (mL >> 3);
  uint32_t baseA = (uint32_t)((rL * 18 + cL) * PST + (lane >> 4) * 16);
  uint32_t baseB = (uint32_t)((lane & 7) * PST + ((lane >> 3) & 1) * 16 + (lane >> 4) * (8 * PST));
  int g = lane >> 2, t4 = lane & 3;

  // stage first y-tile
  {
    int tileY0 = (blockIdx.y * 4) * 8;
    for (int i = tid; i < 1440; i += 256) {
      int r10 = i / 144;
      int rem = i - r10 * 144;
      int c18 = rem >> 3, och = rem & 7;
      int gy = tileY0 - 1 + r10, gx = tileX - 1 + c18;
      uint4 v = make_uint4(0, 0, 0, 0);
      if (gy >= 0 && gy < HH && gx >= 0 && gx < WW)
        v = *(const uint4*)(inH + (((size_t)b * HW + (size_t)gy * WW + gx) * 64 + och * 8));
      *(uint4*)(smem + ACT_H + (r10 * 18 + c18) * PST + och * 16) = v;
    }
  }
  __syncthreads();

  for (int yt = 0; yt < 4; yt++) {
    int tileY = (blockIdx.y * 4 + yt) * 8;

    // prefetch next y-tile into registers
    uint4 pre[6];
    if (yt < 3) {
      int tileYn = tileY + 8;
#pragma unroll
      for (int i2 = 0; i2 < 6; i2++) {
        int idx = tid + 256 * i2;
        uint4 v = make_uint4(0, 0, 0, 0);
        if (idx < 1440) {
          int r10 = idx / 144;
          int rem = idx - r10 * 144;
          int c18 = rem >> 3, och = rem & 7;
          int gy = tileYn - 1 + r10, gx = tileX - 1 + c18;
          if (gy >= 0 && gy < HH && gx >= 0 && gx < WW)
            v = *(const uint4*)(inH + (((size_t)b * HW + (size_t)gy * WW + gx) * 64 + och * 8));
        }
        pre[i2] = v;
      }
    }

    float dacc[8][4];
#pragma unroll
    for (int nb = 0; nb < 8; nb++)
#pragma unroll
      for (int q = 0; q < 4; q++) dacc[nb][q] = 0.f;

#pragma unroll
    for (int t = 0; t < 9; t++) {
      int toff = ((t / 3) * 18 + (t % 3)) * PST;
      uint32_t aH_t = sb + ACT_H + baseA + toff;
      uint32_t wH_t = sb + WGT_H + t * 9216 + baseB;
#pragma unroll
      for (int kb = 0; kb < 4; kb++) {
        uint32_t ah[4], bh[4][4];
        LDM4(ah, aH_t + kb * 32);
#pragma unroll
        for (int j = 0; j < 4; j++) LDM4(bh[j], wH_t + j * 2304 + kb * 32);
#pragma unroll
        for (int j = 0; j < 4; j++) {
          MMA16816(dacc[2 * j], ah, bh[j][0], bh[j][1]);
          MMA16816(dacc[2 * j + 1], ah, bh[j][2], bh[j][3]);
        }
      }
    }

    __syncthreads();
    if (yt < 3) {
#pragma unroll
      for (int i2 = 0; i2 < 6; i2++) {
        int idx = tid + 256 * i2;
        if (idx < 1440) {
          int r10 = idx / 144;
          int rem = idx - r10 * 144;
          int c18 = rem >> 3, och = rem & 7;
          *(uint4*)(smem + ACT_H + (r10 * 18 + c18) * PST + och * 16) = pre[i2];
        }
      }
      __syncthreads();
    }

#pragma unroll
    for (int hrow = 0; hrow < 2; hrow++) {
      int mloc = w * 16 + g + hrow * 8;
      int r = mloc & 7, c = mloc >> 3;
      int py = tileY + r, px = tileX + c;
      size_t pix = (size_t)b * HW + (size_t)py * WW + px;
      float v[16];
#pragma unroll
      for (int nb = 0; nb < 8; nb++) {
        v[2 * nb] = dacc[nb][hrow * 2];
        v[2 * nb + 1] = dacc[nb][hrow * 2 + 1];
      }
      if (use_extra) {
#pragma unroll
        for (int nb = 0; nb < 8; nb++) {
          __half2 e = *(const __half2*)(g_extra + pix * 64 + nb * 8 + t4 * 2);
          v[2 * nb] += __half2float(__low2half(e));
          v[2 * nb + 1] += __half2float(__high2half(e));
        }
        bool interior = (py >= 1 && py <= 254 && px >= 1 && px <= 254);
        if (interior) {
#pragma unroll
          for (int i = 0; i < 16; i++) {
            int ch = (i >> 1) * 8 + t4 * 2 + (i & 1);
            v[i] += Ts_s[ch];
          }
        } else {
          bool vy[3] = {py >= 1, true, py <= 254};
          bool vx[3] = {px >= 1, true, px <= 254};
#pragma unroll
          for (int i = 0; i < 16; i++) {
            int ch = (i >> 1) * 8 + t4 * 2 + (i & 1);
            float s = 0.f;
#pragma unroll
            for (int t = 0; t < 9; t++)
              if (vy[t / 3] && vx[t % 3]) s += T_s[ch * 9 + t];
            v[i] += s;
          }
        }
      }
#pragma unroll
      for (int i = 0; i < 16; i++) {
        int ch = (i >> 1) * 8 + t4 * 2 + (i & 1);
        float val = v[i] * sc_s[ch] + bi_s[ch];
        v[i] = val > 0.f ? val : 0.f;
      }
      if (do_proj) {
        float p0 = 0.f, p1 = 0.f, p2 = 0.f;
#pragma unroll
        for (int i = 0; i < 16; i++) {
          int ch = (i >> 1) * 8 + t4 * 2 + (i & 1);
          p0 += v[i] * wf_s[ch];
          p1 += v[i] * wf_s[64 + ch];
          p2 += v[i] * wf_s[128 + ch];
        }
#pragma unroll
        for (int m2 = 1; m2 <= 2; m2 <<= 1) {
          p0 += __shfl_xor_sync(0xffffffffu, p0, m2);
          p1 += __shfl_xor_sync(0xffffffffu, p1, m2);
          p2 += __shfl_xor_sync(0xffffffffu, p2, m2);
        }
        if (t4 == 0) {
          size_t ob = ((size_t)b * 3) * HW + (size_t)py * WW + px;
          out[ob] = p0 + bf[0];
          out[ob + HW] = p1 + bf[1];
          out[ob + 2 * HW] = p2 + bf[2];
        }
      } else {
#pragma unroll
        for (int nb = 0; nb < 8; nb++) {
          int ch = nb * 8 + t4 * 2;
          *(__half2*)(outH + pix * 64 + ch) =
              __halves2half2(__float2half(v[2 * nb]), __float2half(v[2 * nb + 1]));
        }
      }
    }
  }
}

__global__ void dft_rows_kernel() {
  int n = blockIdx.x, b = blockIdx.y;
  int m = threadIdx.x;
  __shared__ float row[256], twc[256], tws[256], red[16];
  float s, c;
  sincosf((float)m * (TWO_PI / 256.f), &s, &c);
  twc[m] = c; tws[m] = s;
  size_t off = ((size_t)b * HW + (size_t)n * WW + m) * 64;
  row[m] = __half2float(g_aH1[off]);
  __syncthreads();
  float x = row[m];
  int lane = m & 31, wid = m >> 5;
  for (int f = 0; f < 21; f++) {
    int idx = ((118 + f) * m) & 255;
    float pr = x * twc[idx];
    float pi = -x * tws[idx];
#pragma unroll
    for (int o2 = 16; o2 > 0; o2 >>= 1) {
      pr += __shfl_down_sync(0xffffffffu, pr, o2);
      pi += __shfl_down_sync(0xffffffffu, pi, o2);
    }
    if (lane == 0) { red[wid] = pr; red[8 + wid] = pi; }
    __syncthreads();
    if (m == 0) {
      float sr = 0, si = 0;
      for (int w = 0; w < 8; w++) { sr += red[w]; si += red[8 + w]; }
      g_H[((size_t)(b * 21 + f) * 256 + n) * 2] = sr;
      g_H[((size_t)(b * 21 + f) * 256 + n) * 2 + 1] = si;
    }
    __syncthreads();
  }
}

__global__ void dft_points_kernel(const float* __restrict__ message) {
  int b = blockIdx.x;
  int p = threadIdx.x;
  __shared__ float twc[256], tws[256];
  float s, c;
  sincosf((float)p * (TWO_PI / 256.f), &s, &c);
  twc[p] = c; tws[p] = s;
  __syncthreads();
  int yp = g_wy[p], xp = g_wx[p];
  int f = xp - 118;
  const float* Hp = g_H + (size_t)(b * 21 + f) * 512;
  float Fr = 0, Fi = 0;
  for (int n = 0; n < 256; n++) {
    int idx = (yp * n) & 255;
    float cc = twc[idx], ss = tws[idx];
    float hr = Hp[n * 2], hi = Hp[n * 2 + 1];
    Fr += hr * cc + hi * ss;
    Fi += hi * cc - hr * ss;
  }
  float mv = message[b * LL + p];
  g_d[(b * NP + p) * 2] = mv - Fr;
  g_d[(b * NP + p) * 2 + 1] = mv - Fi;
}

__global__ void dft_R_kernel() {
  int yf = blockIdx.x, b = blockIdx.y;
  int m = threadIdx.x;
  __shared__ float twc[256], tws[256], dsr[256], dsi[256];
  float s, c;
  sincosf((float)m * (TWO_PI / 256.f), &s, &c);
  twc[m] = c; tws[m] = s;
  dsr[m] = g_d[(b * NP + m) * 2];
  dsi[m] = g_d[(b * NP + m) * 2 + 1];
  __syncthreads();
  int yv = 118 + yf;
  float ar = 0, ai = 0;
  for (int p = 0; p < NP; p++) {
    if (g_wy[p] == yv) {
      int idx = (g_wx[p] * m) & 255;
      float cc = twc[idx], ss = tws[idx];
      float dr = dsr[p], di = dsi[p];
      ar += dr * cc - di * ss;
      ai += dr * ss + di * cc;
    }
  }
  g_R[((size_t)(b * 16 + yf) * 256 + m) * 2] = ar;
  g_R[((size_t)(b * 16 + yf) * 256 + m) * 2 + 1] = ai;
}

__global__ void dft_corr_kernel() {
  int n = blockIdx.x, b = blockIdx.y;
  int m = threadIdx.x;
  __shared__ float twc[256], tws[256];
  float s, c;
  sincosf((float)m * (TWO_PI / 256.f), &s, &c);
  twc[m] = c; tws[m] = s;
  __syncthreads();
  float acc = 0.f;
#pragma unroll
  for (int yf = 0; yf < 16; yf++) {
    int idx = ((118 + yf) * n) & 255;
    float cc = twc[idx], ss = tws[idx];
    float Rr = g_R[((size_t)(b * 16 + yf) * 256 + m) * 2];
    float Ri = g_R[((size_t)(b * 16 + yf) * 256 + m) * 2 + 1];
    acc += cc * Rr - ss * Ri;
  }
  size_t off = ((size_t)b * HW + (size_t)n * WW + m) * 64;
  float v = __half2float(g_aH1[off]) + acc * (1.0f / 65536.0f);
  g_aH1[off] = __float2half(v);
}

extern "C" void kernel_launch(void* const* d_in, const int* in_sizes, int n_in,
                              void* d_out, int out_size) {
  const float* image   = (const float*)d_in[0];
  const float* message = (const float*)d_in[1];
  const float* w0  = (const float*)d_in[2];
  const float* b0  = (const float*)d_in[3];
  const float* g0  = (const float*)d_in[4];
  const float* be0 = (const float*)d_in[5];
  const float* m0  = (const float*)d_in[6];
  const float* v0  = (const float*)d_in[7];
  const float* wk  = (const float*)d_in[8];
  const float* bk  = (const float*)d_in[9];
  const float* gk  = (const float*)d_in[10];
  const float* bek = (const float*)d_in[11];
  const float* mk  = (const float*)d_in[12];
  const float* vk  = (const float*)d_in[13];
  const float* wa  = (const float*)d_in[14];
  const float* ba  = (const float*)d_in[15];
  const float* ga  = (const float*)d_in[16];
  const float* bea = (const float*)d_in[17];
  const float* ma  = (const float*)d_in[18];
  const float* va  = (const float*)d_in[19];
  const float* wf  = (const float*)d_in[20];
  const float* bf  = (const float*)d_in[21];
  float* out = (float*)d_out;

  cudaFuncSetAttribute(conv_mma_kernel, cudaFuncAttributeMaxDynamicSharedMemorySize, SMEM_MMA_TOTAL);

  prep_kernel<<<1, 256>>>(b0, g0, be0, m0, v0, bk, gk, bek, mk, vk, ba, ga, bea, ma, va);
  prep_w_kernel<<<576, 256>>>(wk, wa);
  prep_w3_kernel<<<16, 256>>>(w0, wa);
  msgT_kernel<<<dim3(8, NB), 256>>>(message, wa);

  conv3_mma_kernel<<<dim3(16, 32, NB), 256>>>(image);

  dim3 mg(WW / 16, 8, NB);
  conv_mma_kernel<<<mg, 256, SMEM_MMA_TOTAL>>>(0, 0, 1, 0, 0, nullptr, nullptr, nullptr);
  conv_mma_kernel<<<mg, 256, SMEM_MMA_TOTAL>>>(1, 1, 2, 0, 0, nullptr, nullptr, nullptr);
  conv_mma_kernel<<<mg, 256, SMEM_MMA_TOTAL>>>(0, 2, 3, 0, 0, nullptr, nullptr, nullptr);

  dft_rows_kernel<<<dim3(256, NB), 256>>>();
  dft_points_kernel<<<NB, 256>>>(message);
  dft_R_kernel<<<dim3(16, NB), 256>>>();
  dft_corr_kernel<<<dim3(256, NB), 256>>>();

  conv_mma_kernel<<<dim3(16, 8, NB), 256, SMEM_MMA_TOTAL>>>(1, 3, 4, 1, 1, wf, bf, out);
}